// round 14
// baseline (speedup 1.0000x reference)
#include <cuda_runtime.h>

#define NTH  256

struct Params { const float* p[27]; };

// Exact leaky-relu slope 0.0025: rr(v) = max(v, 0.0025*v).
__device__ __forceinline__ float rr(float v) {
    return fmaxf(v, 0.0025f * v);
}

// ---- constant-memory layout (floats); W/b offsets 16B-aligned for LDC.128 ----
// W_in stored TRANSPOSED: c_s[j*8+i] = W_in[i][j]
#define O_WIN_T  0      // 64
#define O_B_IN   64     // 8
#define O_W_H1   72     // [8][4] row-major, 32
#define O_B_H1   104    // 4
#define O_W_H2   108
#define O_B_H2   124
#define O_W_H3   128
#define O_B_H3   144
#define O_W_H4   148
#define O_B_H4   164
#define O_W_H5   168
#define O_B_H5   184
#define O_W_EN   188    // 4
#define O_B_EN   192    // 1 (+3 pad)
#define O_W_H6   196    // 4
#define O_B_H6   200    // 4
#define O_W_H7   204
#define O_B_H7   220
#define O_W_H8   224
#define O_B_H8   240
#define O_W_H9   244
#define O_B_H9   260
#define O_W_HA   264
#define O_B_HA   280
#define O_W_DE   284    // [4][8] row-major, 32
#define O_B_DE   316    // 8
#define S_TOTAL  324

// ---- shared-memory layout for the port-split (residual blocks + decode) ----
// Each entry is W (16 or 32) immediately followed by b (4 or 8), mirroring c_s.
#define SW_H2    0      // W(16)+b(4)
#define SW_H3    20
#define SW_H4    40
#define SW_H5    60
#define SW_H7    80
#define SW_H8    100
#define SW_H9    120
#define SW_HA    140
#define SW_DE    160    // W(32)+b(8)
#define SW_TOTAL 200

__constant__ float c_s[S_TOTAL];
__device__   float g_stage[S_TOTAL];   // static scratch (no allocation)

// Fully parallel gather: one thread per destination slot, one LDG + one STG each.
__global__ void gather_weights(Params P) {
    int i = threadIdx.x;
    if (i >= S_TOTAL) return;

    float v = 0.f;                       // pad slots (193..195) -> 0
    if (i < O_B_IN) {
        int j = i >> 3, ii = i & 7;
        v = P.p[1][ii * 8 + j];          // transposed W_in
    } else {
        const short off[26] = {O_B_IN,O_W_H1,O_B_H1,O_W_H2,O_B_H2,O_W_H3,O_B_H3,
                               O_W_H4,O_B_H4,O_W_H5,O_B_H5,O_W_EN,O_B_EN,O_W_H6,O_B_H6,
                               O_W_H7,O_B_H7,O_W_H8,O_B_H8,O_W_H9,O_B_H9,O_W_HA,O_B_HA,
                               O_W_DE,O_B_DE,S_TOTAL};
        const short cnt[25] = {8,32,4,16,4,16,4,16,4,16,4,4,1,4,4,16,4,16,4,16,4,16,4,32,8};
#pragma unroll
        for (int k = 0; k < 25; k++) {
            int rel = i - off[k];
            if (rel >= 0 && rel < cnt[k]) v = P.p[k + 2][rel];
        }
    }
    g_stage[i] = v;
}

__device__ __forceinline__ float4 ld4c(int off) {
    return *reinterpret_cast<const float4*>(c_s + off);
}
__device__ __forceinline__ float4 ld4p(const float* p, int off) {
    return *reinterpret_cast<const float4*>(p + off);
}

// 4x4 layer for 4 rows from SHARED memory (LDS.128 broadcast, LSU port):
// weights at base+0..15, bias at base+16.
template<bool ACT, bool RESID>
__device__ __forceinline__ void lin44s(const float* __restrict__ sw, int base,
                                       const float (&src)[4][4], float (&dst)[4][4]) {
    float4 b = ld4p(sw, base + 16);
    float acc[4][4];
#pragma unroll
    for (int r = 0; r < 4; r++) {
        acc[r][0] = b.x; acc[r][1] = b.y; acc[r][2] = b.z; acc[r][3] = b.w;
    }
#pragma unroll
    for (int i = 0; i < 4; i++) {
        float4 w = ld4p(sw, base + 4 * i);
#pragma unroll
        for (int r = 0; r < 4; r++) {
            acc[r][0] = fmaf(src[r][i], w.x, acc[r][0]);
            acc[r][1] = fmaf(src[r][i], w.y, acc[r][1]);
            acc[r][2] = fmaf(src[r][i], w.z, acc[r][2]);
            acc[r][3] = fmaf(src[r][i], w.w, acc[r][3]);
        }
    }
#pragma unroll
    for (int r = 0; r < 4; r++)
#pragma unroll
        for (int j = 0; j < 4; j++)
            dst[r][j] = RESID ? (dst[r][j] + acc[r][j]) : (ACT ? rr(acc[r][j]) : acc[r][j]);
}

template<bool GUARD>
__global__ __launch_bounds__(NTH, 4)
void ann_fused_kernel(const float* __restrict__ xin, float* __restrict__ out, int N) {
    __shared__ alignas(16) float sw[SW_TOTAL];

    // Stage residual-block + decode weights const -> shared (one LDC+STS per thread).
    {
        int i = threadIdx.x;
        if (i < 160) {
            const short cbase[8] = {O_W_H2, O_W_H3, O_W_H4, O_W_H5,
                                    O_W_H7, O_W_H8, O_W_H9, O_W_HA};
            sw[i] = c_s[cbase[i / 20] + i % 20];
        } else if (i < SW_TOTAL) {
            sw[i] = c_s[O_W_DE + (i - 160)];
        }
    }
    __syncthreads();

    unsigned base = blockIdx.x * (4 * NTH) + threadIdx.x;

    // ---- fused in+h1 (constant port), 2 rows at a time to cap liveness ----
    float x[4][4];
    {
        float4 bh1 = ld4c(O_B_H1);
#pragma unroll
        for (int r = 0; r < 4; r++) {
            x[r][0]=bh1.x; x[r][1]=bh1.y; x[r][2]=bh1.z; x[r][3]=bh1.w;
        }
#pragma unroll
        for (int pp = 0; pp < 2; pp++) {
            unsigned rA = base + (2 * pp) * NTH;
            unsigned rB = rA + NTH;
            float xa[8], xb[8];
            if (!GUARD || rA < (unsigned)N) {
                float4 a0 = __ldcs(reinterpret_cast<const float4*>(xin + (size_t)rA * 8));
                float4 a1 = __ldcs(reinterpret_cast<const float4*>(xin + (size_t)rA * 8 + 4));
                xa[0]=a0.x; xa[1]=a0.y; xa[2]=a0.z; xa[3]=a0.w;
                xa[4]=a1.x; xa[5]=a1.y; xa[6]=a1.z; xa[7]=a1.w;
            } else {
#pragma unroll
                for (int i = 0; i < 8; i++) xa[i] = 0.f;
            }
            if (!GUARD || rB < (unsigned)N) {
                float4 b0 = __ldcs(reinterpret_cast<const float4*>(xin + (size_t)rB * 8));
                float4 b1 = __ldcs(reinterpret_cast<const float4*>(xin + (size_t)rB * 8 + 4));
                xb[0]=b0.x; xb[1]=b0.y; xb[2]=b0.z; xb[3]=b0.w;
                xb[4]=b1.x; xb[5]=b1.y; xb[6]=b1.z; xb[7]=b1.w;
            } else {
#pragma unroll
                for (int i = 0; i < 8; i++) xb[i] = 0.f;
            }
#pragma unroll
            for (int j = 0; j < 8; j++) {
                float bj = c_s[O_B_IN + j];
                float4 w0 = ld4c(O_WIN_T + j * 8);
                float4 w1 = ld4c(O_WIN_T + j * 8 + 4);
                float va = bj, vb = bj;
                va = fmaf(xa[0], w0.x, va); vb = fmaf(xb[0], w0.x, vb);
                va = fmaf(xa[1], w0.y, va); vb = fmaf(xb[1], w0.y, vb);
                va = fmaf(xa[2], w0.z, va); vb = fmaf(xb[2], w0.z, vb);
                va = fmaf(xa[3], w0.w, va); vb = fmaf(xb[3], w0.w, vb);
                va = fmaf(xa[4], w1.x, va); vb = fmaf(xb[4], w1.x, vb);
                va = fmaf(xa[5], w1.y, va); vb = fmaf(xb[5], w1.y, vb);
                va = fmaf(xa[6], w1.z, va); vb = fmaf(xb[6], w1.z, vb);
                va = fmaf(xa[7], w1.w, va); vb = fmaf(xb[7], w1.w, vb);
                va = rr(va); vb = rr(vb);
                float4 h = ld4c(O_W_H1 + j * 4);
                x[2*pp  ][0] = fmaf(va, h.x, x[2*pp  ][0]);
                x[2*pp  ][1] = fmaf(va, h.y, x[2*pp  ][1]);
                x[2*pp  ][2] = fmaf(va, h.z, x[2*pp  ][2]);
                x[2*pp  ][3] = fmaf(va, h.w, x[2*pp  ][3]);
                x[2*pp+1][0] = fmaf(vb, h.x, x[2*pp+1][0]);
                x[2*pp+1][1] = fmaf(vb, h.y, x[2*pp+1][1]);
                x[2*pp+1][2] = fmaf(vb, h.z, x[2*pp+1][2]);
                x[2*pp+1][3] = fmaf(vb, h.w, x[2*pp+1][3]);
            }
        }
    }

    float t[4][4];

    // ---- encoder residual blocks (shared port) ----
    lin44s<true,  false>(sw, SW_H2, x, t);
    lin44s<false, true >(sw, SW_H3, t, x);
    lin44s<true,  false>(sw, SW_H4, x, t);
    lin44s<false, true >(sw, SW_H5, t, x);

    // ---- encode (4 -> 1, constant port) + store ----
    float e[4];
    {
        float4 we = ld4c(O_W_EN);
        float be = c_s[O_B_EN];
#pragma unroll
        for (int r = 0; r < 4; r++) {
            float v = be;
            v = fmaf(x[r][0], we.x, v); v = fmaf(x[r][1], we.y, v);
            v = fmaf(x[r][2], we.z, v); v = fmaf(x[r][3], we.w, v);
            e[r] = rr(v);
        }
    }
#pragma unroll
    for (int r = 0; r < 4; r++) {
        unsigned row = base + r * NTH;
        if (!GUARD || row < (unsigned)N) __stcs(out + row, e[r]);
    }

    // ---- h6 (1 -> 4, constant port) ----
    {
        float4 w6 = ld4c(O_W_H6);
        float4 b6 = ld4c(O_B_H6);
#pragma unroll
        for (int r = 0; r < 4; r++) {
            x[r][0] = rr(fmaf(e[r], w6.x, b6.x));
            x[r][1] = rr(fmaf(e[r], w6.y, b6.y));
            x[r][2] = rr(fmaf(e[r], w6.z, b6.z));
            x[r][3] = rr(fmaf(e[r], w6.w, b6.w));
        }
    }

    // ---- decoder residual blocks (shared port) ----
    lin44s<true,  false>(sw, SW_H7, x, t);
    lin44s<false, true >(sw, SW_H8, t, x);
    lin44s<true,  false>(sw, SW_H9, x, t);
    lin44s<false, true >(sw, SW_HA, t, x);

    // ---- decode (4 -> 8, shared port) + store, 2 rows at a time ----
    float* __restrict__ dec = out + N;
    float4 b0 = ld4p(sw, SW_DE + 32);
    float4 b1 = ld4p(sw, SW_DE + 36);
#pragma unroll
    for (int pp = 0; pp < 2; pp++) {
        float da[8], db[8];
        da[0]=b0.x; da[1]=b0.y; da[2]=b0.z; da[3]=b0.w;
        da[4]=b1.x; da[5]=b1.y; da[6]=b1.z; da[7]=b1.w;
#pragma unroll
        for (int j = 0; j < 8; j++) db[j] = da[j];
#pragma unroll
        for (int i = 0; i < 4; i++) {
            float4 w0 = ld4p(sw, SW_DE + i * 8);
            float4 w1 = ld4p(sw, SW_DE + i * 8 + 4);
            float va = x[2*pp][i], vb = x[2*pp+1][i];
            da[0] = fmaf(va, w0.x, da[0]); db[0] = fmaf(vb, w0.x, db[0]);
            da[1] = fmaf(va, w0.y, da[1]); db[1] = fmaf(vb, w0.y, db[1]);
            da[2] = fmaf(va, w0.z, da[2]); db[2] = fmaf(vb, w0.z, db[2]);
            da[3] = fmaf(va, w0.w, da[3]); db[3] = fmaf(vb, w0.w, db[3]);
            da[4] = fmaf(va, w1.x, da[4]); db[4] = fmaf(vb, w1.x, db[4]);
            da[5] = fmaf(va, w1.y, da[5]); db[5] = fmaf(vb, w1.y, db[5]);
            da[6] = fmaf(va, w1.z, da[6]); db[6] = fmaf(vb, w1.z, db[6]);
            da[7] = fmaf(va, w1.w, da[7]); db[7] = fmaf(vb, w1.w, db[7]);
        }
        unsigned rA = base + (2 * pp) * NTH;
        unsigned rB = rA + NTH;
        if (!GUARD || rA < (unsigned)N) {
            __stcs(reinterpret_cast<float4*>(dec + (size_t)rA * 8),
                   make_float4(rr(da[0]), rr(da[1]), rr(da[2]), rr(da[3])));
            __stcs(reinterpret_cast<float4*>(dec + (size_t)rA * 8 + 4),
                   make_float4(rr(da[4]), rr(da[5]), rr(da[6]), rr(da[7])));
        }
        if (!GUARD || rB < (unsigned)N) {
            __stcs(reinterpret_cast<float4*>(dec + (size_t)rB * 8),
                   make_float4(rr(db[0]), rr(db[1]), rr(db[2]), rr(db[3])));
            __stcs(reinterpret_cast<float4*>(dec + (size_t)rB * 8 + 4),
                   make_float4(rr(db[4]), rr(db[5]), rr(db[6]), rr(db[7])));
        }
    }
}

extern "C" void kernel_launch(void* const* d_in, const int* in_sizes, int n_in,
                              void* d_out, int out_size) {
    Params P;
    for (int k = 0; k < 27; k++) P.p[k] = (const float*)d_in[k];
    int N = in_sizes[0] / 8;                 // 4194304 rows

    gather_weights<<<1, 352>>>(P);
    void* stage_ptr = nullptr;
    cudaGetSymbolAddress(&stage_ptr, g_stage);
    cudaMemcpyToSymbolAsync(c_s, stage_ptr, S_TOTAL * sizeof(float), 0,
                            cudaMemcpyDeviceToDevice, 0);

    int rows_per_block = 4 * NTH;            // 1024
    int blocks = (N + rows_per_block - 1) / rows_per_block;
    if (N % rows_per_block == 0)
        ann_fused_kernel<false><<<blocks, NTH>>>((const float*)d_in[0], (float*)d_out, N);
    else
        ann_fused_kernel<true ><<<blocks, NTH>>>((const float*)d_in[0], (float*)d_out, N);
}

// round 15
// speedup vs baseline: 1.1231x; 1.1231x over previous
#include <cuda_runtime.h>

#define NTH  256
typedef unsigned long long u64;

struct Params { const float* p[27]; };

// ---------- packed f32x2 primitives (sm_103a) ----------
__device__ __forceinline__ u64 ffma2(u64 a, u64 b, u64 c) {
    u64 d; asm("fma.rn.f32x2 %0,%1,%2,%3;" : "=l"(d) : "l"(a), "l"(b), "l"(c)); return d;
}
__device__ __forceinline__ u64 fmul2(u64 a, u64 b) {
    u64 d; asm("mul.rn.f32x2 %0,%1,%2;" : "=l"(d) : "l"(a), "l"(b)); return d;
}
__device__ __forceinline__ u64 fadd2(u64 a, u64 b) {
    u64 d; asm("add.rn.f32x2 %0,%1,%2;" : "=l"(d) : "l"(a), "l"(b)); return d;
}
__device__ __forceinline__ u64 pack2(float lo, float hi) {
    u64 d; asm("mov.b64 %0,{%1,%2};" : "=l"(d) : "f"(lo), "f"(hi)); return d;
}
__device__ __forceinline__ void unpack2(u64 v, float& lo, float& hi) {
    asm("mov.b64 {%0,%1},%2;" : "=f"(lo), "=f"(hi) : "l"(v));
}
__device__ __forceinline__ u64 abs2(u64 v) {
    u64 d; asm("and.b64 %0,%1,0x7FFFFFFF7FFFFFFF;" : "=l"(d) : "l"(v)); return d;
}
// Packed branchless leaky-relu (slope 0.0025): rr(v)=0.50125*v+0.49875*|v|.
__device__ __forceinline__ u64 rr2(u64 v) {
    const u64 C1 = pack2(0.50125f, 0.50125f);
    const u64 C2 = pack2(0.49875f, 0.49875f);
    return ffma2(v, C1, fmul2(abs2(v), C2));
}

// ---- constant layout, u64 slots (each scalar weight DUPLICATED into both lanes).
// Offsets identical to the float layout; all even -> 16B-aligned paired LDC.128.
#define O_WIN_T  0      // 64  (W_in transposed)
#define O_B_IN   64     // 8
#define O_W_H1   72     // 32
#define O_B_H1   104    // 4
#define O_W_H2   108
#define O_B_H2   124
#define O_W_H3   128
#define O_B_H3   144
#define O_W_H4   148
#define O_B_H4   164
#define O_W_H5   168
#define O_B_H5   184
#define O_W_EN   188    // 4
#define O_B_EN   192    // 1 (+3 pad)
#define O_W_H6   196    // 4
#define O_B_H6   200    // 4
#define O_W_H7   204
#define O_B_H7   220
#define O_W_H8   224
#define O_B_H8   240
#define O_W_H9   244
#define O_B_H9   260
#define O_W_HA   264
#define O_B_HA   280
#define O_W_DE   284    // 32
#define O_B_DE   316    // 8
#define S_TOTAL  324

__constant__ __align__(16) u64 c_d[S_TOTAL];
__device__  __align__(16) u64 g_stage[S_TOTAL];   // static scratch

// Fully parallel gather: one thread per slot, duplicate scalar into both lanes.
__global__ void gather_weights(Params P) {
    int i = threadIdx.x;
    if (i >= S_TOTAL) return;

    float v = 0.f;
    if (i < O_B_IN) {
        int j = i >> 3, ii = i & 7;
        v = P.p[1][ii * 8 + j];          // transposed W_in
    } else {
        const short off[26] = {O_B_IN,O_W_H1,O_B_H1,O_W_H2,O_B_H2,O_W_H3,O_B_H3,
                               O_W_H4,O_B_H4,O_W_H5,O_B_H5,O_W_EN,O_B_EN,O_W_H6,O_B_H6,
                               O_W_H7,O_B_H7,O_W_H8,O_B_H8,O_W_H9,O_B_H9,O_W_HA,O_B_HA,
                               O_W_DE,O_B_DE,S_TOTAL};
        const short cnt[25] = {8,32,4,16,4,16,4,16,4,16,4,4,1,4,4,16,4,16,4,16,4,16,4,32,8};
#pragma unroll
        for (int k = 0; k < 25; k++) {
            int rel = i - off[k];
            if (rel >= 0 && rel < cnt[k]) v = P.p[k + 2][rel];
        }
    }
    unsigned u = __float_as_uint(v);
    g_stage[i] = ((u64)u << 32) | u;
}

// one LDC.128 -> two duplicated-weight u64 operands (off must be even)
__device__ __forceinline__ ulonglong2 ld2c(int off) {
    return *reinterpret_cast<const ulonglong2*>(c_d + off);
}

// 4x4 layer for BOTH row-pairs, packed: 16 FFMA2, 10 LDC.128-halves.
template<bool ACT, bool RESID>
__device__ __forceinline__ void lin44p(int Woff, int boff,
                                       const u64 (&src)[2][4], u64 (&dst)[2][4]) {
    ulonglong2 bb0 = ld2c(boff);
    ulonglong2 bb1 = ld2c(boff + 2);
    u64 acc[2][4];
#pragma unroll
    for (int p = 0; p < 2; p++) {
        acc[p][0] = bb0.x; acc[p][1] = bb0.y; acc[p][2] = bb1.x; acc[p][3] = bb1.y;
    }
#pragma unroll
    for (int i = 0; i < 4; i++) {
        ulonglong2 wA = ld2c(Woff + 4 * i);
        ulonglong2 wB = ld2c(Woff + 4 * i + 2);
#pragma unroll
        for (int p = 0; p < 2; p++) {
            acc[p][0] = ffma2(src[p][i], wA.x, acc[p][0]);
            acc[p][1] = ffma2(src[p][i], wA.y, acc[p][1]);
            acc[p][2] = ffma2(src[p][i], wB.x, acc[p][2]);
            acc[p][3] = ffma2(src[p][i], wB.y, acc[p][3]);
        }
    }
#pragma unroll
    for (int p = 0; p < 2; p++)
#pragma unroll
        for (int j = 0; j < 4; j++)
            dst[p][j] = RESID ? fadd2(dst[p][j], acc[p][j])
                              : (ACT ? rr2(acc[p][j]) : acc[p][j]);
}

template<bool GUARD>
__global__ __launch_bounds__(NTH, 4)
void ann_fused_kernel(const float* __restrict__ xin, float* __restrict__ out, int N) {
    unsigned base = blockIdx.x * (4 * NTH) + threadIdx.x;
    // pair p covers rows (base + 2p*NTH, base + (2p+1)*NTH)

    // ---- fused in+h1, one pair at a time (low liveness) ----
    u64 x[2][4];
#pragma unroll
    for (int pp = 0; pp < 2; pp++) {
        unsigned rA = base + (2 * pp) * NTH;
        unsigned rB = rA + NTH;
        u64 xp[8];
        {
            float4 a0, a1, b0, b1;
            if (!GUARD || rA < (unsigned)N) {
                a0 = __ldcs(reinterpret_cast<const float4*>(xin + (size_t)rA * 8));
                a1 = __ldcs(reinterpret_cast<const float4*>(xin + (size_t)rA * 8 + 4));
            } else { a0 = a1 = make_float4(0.f,0.f,0.f,0.f); }
            if (!GUARD || rB < (unsigned)N) {
                b0 = __ldcs(reinterpret_cast<const float4*>(xin + (size_t)rB * 8));
                b1 = __ldcs(reinterpret_cast<const float4*>(xin + (size_t)rB * 8 + 4));
            } else { b0 = b1 = make_float4(0.f,0.f,0.f,0.f); }
            xp[0] = pack2(a0.x, b0.x); xp[1] = pack2(a0.y, b0.y);
            xp[2] = pack2(a0.z, b0.z); xp[3] = pack2(a0.w, b0.w);
            xp[4] = pack2(a1.x, b1.x); xp[5] = pack2(a1.y, b1.y);
            xp[6] = pack2(a1.z, b1.z); xp[7] = pack2(a1.w, b1.w);
        }
        {
            ulonglong2 bb0 = ld2c(O_B_H1);
            ulonglong2 bb1 = ld2c(O_B_H1 + 2);
            x[pp][0] = bb0.x; x[pp][1] = bb0.y; x[pp][2] = bb1.x; x[pp][3] = bb1.y;
        }
#pragma unroll
        for (int j = 0; j < 8; j++) {
            u64 v = c_d[O_B_IN + j];                    // LDC.64 (dup bias)
            ulonglong2 w01 = ld2c(O_WIN_T + j * 8);
            ulonglong2 w23 = ld2c(O_WIN_T + j * 8 + 2);
            ulonglong2 w45 = ld2c(O_WIN_T + j * 8 + 4);
            ulonglong2 w67 = ld2c(O_WIN_T + j * 8 + 6);
            v = ffma2(xp[0], w01.x, v); v = ffma2(xp[1], w01.y, v);
            v = ffma2(xp[2], w23.x, v); v = ffma2(xp[3], w23.y, v);
            v = ffma2(xp[4], w45.x, v); v = ffma2(xp[5], w45.y, v);
            v = ffma2(xp[6], w67.x, v); v = ffma2(xp[7], w67.y, v);
            v = rr2(v);
            ulonglong2 h01 = ld2c(O_W_H1 + j * 4);
            ulonglong2 h23 = ld2c(O_W_H1 + j * 4 + 2);
            x[pp][0] = ffma2(v, h01.x, x[pp][0]);
            x[pp][1] = ffma2(v, h01.y, x[pp][1]);
            x[pp][2] = ffma2(v, h23.x, x[pp][2]);
            x[pp][3] = ffma2(v, h23.y, x[pp][3]);
        }
    }

    u64 t[2][4];

    // ---- encoder residual blocks ----
    lin44p<true,  false>(O_W_H2, O_B_H2, x, t);
    lin44p<false, true >(O_W_H3, O_B_H3, t, x);
    lin44p<true,  false>(O_W_H4, O_B_H4, x, t);
    lin44p<false, true >(O_W_H5, O_B_H5, t, x);

    // ---- encode (4 -> 1) + store ----
    u64 e[2];
    {
        ulonglong2 we0 = ld2c(O_W_EN);
        ulonglong2 we1 = ld2c(O_W_EN + 2);
        u64 be = c_d[O_B_EN];
#pragma unroll
        for (int p = 0; p < 2; p++) {
            u64 v = be;
            v = ffma2(x[p][0], we0.x, v); v = ffma2(x[p][1], we0.y, v);
            v = ffma2(x[p][2], we1.x, v); v = ffma2(x[p][3], we1.y, v);
            e[p] = rr2(v);
        }
    }
#pragma unroll
    for (int p = 0; p < 2; p++) {
        unsigned rA = base + (2 * p) * NTH;
        unsigned rB = rA + NTH;
        float eA, eB;
        unpack2(e[p], eA, eB);
        if (!GUARD || rA < (unsigned)N) __stcs(out + rA, eA);
        if (!GUARD || rB < (unsigned)N) __stcs(out + rB, eB);
    }

    // ---- h6 (1 -> 4) ----
    {
        ulonglong2 w60 = ld2c(O_W_H6);
        ulonglong2 w61 = ld2c(O_W_H6 + 2);
        ulonglong2 b60 = ld2c(O_B_H6);
        ulonglong2 b61 = ld2c(O_B_H6 + 2);
#pragma unroll
        for (int p = 0; p < 2; p++) {
            x[p][0] = rr2(ffma2(e[p], w60.x, b60.x));
            x[p][1] = rr2(ffma2(e[p], w60.y, b60.y));
            x[p][2] = rr2(ffma2(e[p], w61.x, b61.x));
            x[p][3] = rr2(ffma2(e[p], w61.y, b61.y));
        }
    }

    // ---- decoder residual blocks ----
    lin44p<true,  false>(O_W_H7, O_B_H7, x, t);
    lin44p<false, true >(O_W_H8, O_B_H8, t, x);
    lin44p<true,  false>(O_W_H9, O_B_H9, x, t);
    lin44p<false, true >(O_W_HA, O_B_HA, t, x);

    // ---- decode (4 -> 8) + store, one pair at a time (low tail liveness) ----
    float* __restrict__ dec = out + N;
#pragma unroll
    for (int pp = 0; pp < 2; pp++) {
        u64 d[8];
        {
            ulonglong2 b0 = ld2c(O_B_DE);
            ulonglong2 b1 = ld2c(O_B_DE + 2);
            ulonglong2 b2 = ld2c(O_B_DE + 4);
            ulonglong2 b3 = ld2c(O_B_DE + 6);
            d[0]=b0.x; d[1]=b0.y; d[2]=b1.x; d[3]=b1.y;
            d[4]=b2.x; d[5]=b2.y; d[6]=b3.x; d[7]=b3.y;
        }
#pragma unroll
        for (int i = 0; i < 4; i++) {
            ulonglong2 w0 = ld2c(O_W_DE + i * 8);
            ulonglong2 w1 = ld2c(O_W_DE + i * 8 + 2);
            ulonglong2 w2 = ld2c(O_W_DE + i * 8 + 4);
            ulonglong2 w3 = ld2c(O_W_DE + i * 8 + 6);
            u64 v = x[pp][i];
            d[0] = ffma2(v, w0.x, d[0]); d[1] = ffma2(v, w0.y, d[1]);
            d[2] = ffma2(v, w1.x, d[2]); d[3] = ffma2(v, w1.y, d[3]);
            d[4] = ffma2(v, w2.x, d[4]); d[5] = ffma2(v, w2.y, d[5]);
            d[6] = ffma2(v, w3.x, d[6]); d[7] = ffma2(v, w3.y, d[7]);
        }
        unsigned rA = base + (2 * pp) * NTH;
        unsigned rB = rA + NTH;
        float a[8], b[8];
#pragma unroll
        for (int j = 0; j < 8; j++) { d[j] = rr2(d[j]); unpack2(d[j], a[j], b[j]); }
        if (!GUARD || rA < (unsigned)N) {
            __stcs(reinterpret_cast<float4*>(dec + (size_t)rA * 8),
                   make_float4(a[0], a[1], a[2], a[3]));
            __stcs(reinterpret_cast<float4*>(dec + (size_t)rA * 8 + 4),
                   make_float4(a[4], a[5], a[6], a[7]));
        }
        if (!GUARD || rB < (unsigned)N) {
            __stcs(reinterpret_cast<float4*>(dec + (size_t)rB * 8),
                   make_float4(b[0], b[1], b[2], b[3]));
            __stcs(reinterpret_cast<float4*>(dec + (size_t)rB * 8 + 4),
                   make_float4(b[4], b[5], b[6], b[7]));
        }
    }
}

extern "C" void kernel_launch(void* const* d_in, const int* in_sizes, int n_in,
                              void* d_out, int out_size) {
    Params P;
    for (int k = 0; k < 27; k++) P.p[k] = (const float*)d_in[k];
    int N = in_sizes[0] / 8;                 // 4194304 rows

    gather_weights<<<1, 352>>>(P);
    void* stage_ptr = nullptr;
    cudaGetSymbolAddress(&stage_ptr, g_stage);
    cudaMemcpyToSymbolAsync(c_d, stage_ptr, S_TOTAL * sizeof(u64), 0,
                            cudaMemcpyDeviceToDevice, 0);

    int rows_per_block = 4 * NTH;            // 1024
    int blocks = (N + rows_per_block - 1) / rows_per_block;
    if (N % rows_per_block == 0)
        ann_fused_kernel<false><<<blocks, NTH>>>((const float*)d_in[0], (float*)d_out, N);
    else
        ann_fused_kernel<true ><<<blocks, NTH>>>((const float*)d_in[0], (float*)d_out, N);
}

// round 16
// speedup vs baseline: 1.2964x; 1.1543x over previous
#include <cuda_runtime.h>

#define NTH  256

struct Params { const float* p[27]; };

// Exact leaky-relu slope 0.0025: rr(v) = max(v, 0.0025*v).
__device__ __forceinline__ float rr(float v) {
    return fmaxf(v, 0.0025f * v);
}

// ---- constant-memory layout (floats); W/b offsets 16B-aligned for LDC.128 ----
// W_in stored TRANSPOSED: c_s[j*8+i] = W_in[i][j]
#define O_WIN_T  0      // 64
#define O_B_IN   64     // 8
#define O_W_H1   72     // [8][4] row-major, 32
#define O_B_H1   104    // 4
#define O_W_H2   108
#define O_B_H2   124
#define O_W_H3   128
#define O_B_H3   144
#define O_W_H4   148
#define O_B_H4   164
#define O_W_H5   168
#define O_B_H5   184
#define O_W_EN   188    // 4
#define O_B_EN   192    // 1 (+3 pad)
#define O_W_H6   196    // 4
#define O_B_H6   200    // 4
#define O_W_H7   204
#define O_B_H7   220
#define O_W_H8   224
#define O_B_H8   240
#define O_W_H9   244
#define O_B_H9   260
#define O_W_HA   264
#define O_B_HA   280
#define O_W_DE   284    // [4][8] row-major, 32
#define O_B_DE   316    // 8
#define S_TOTAL  324

__constant__ float c_s[S_TOTAL];
__device__   float g_stage[S_TOTAL];   // static scratch (no allocation)

// Fully parallel gather: one thread per destination slot, one LDG + one STG each.
__global__ void gather_weights(Params P) {
    int i = threadIdx.x;
    if (i >= S_TOTAL) return;

    float v = 0.f;                       // pad slots (193..195) -> 0
    if (i < O_B_IN) {
        int j = i >> 3, ii = i & 7;
        v = P.p[1][ii * 8 + j];          // transposed W_in
    } else {
        const short off[26] = {O_B_IN,O_W_H1,O_B_H1,O_W_H2,O_B_H2,O_W_H3,O_B_H3,
                               O_W_H4,O_B_H4,O_W_H5,O_B_H5,O_W_EN,O_B_EN,O_W_H6,O_B_H6,
                               O_W_H7,O_B_H7,O_W_H8,O_B_H8,O_W_H9,O_B_H9,O_W_HA,O_B_HA,
                               O_W_DE,O_B_DE,S_TOTAL};
        const short cnt[25] = {8,32,4,16,4,16,4,16,4,16,4,4,1,4,4,16,4,16,4,16,4,16,4,32,8};
#pragma unroll
        for (int k = 0; k < 25; k++) {
            int rel = i - off[k];
            if (rel >= 0 && rel < cnt[k]) v = P.p[k + 2][rel];
        }
    }
    g_stage[i] = v;
}

__device__ __forceinline__ float4 ld4c(int off) {
    return *reinterpret_cast<const float4*>(c_s + off);
}

// 4x4 layer for 4 rows, j-vectorized: 5 LDC.128 (const port, not LSU).
template<bool ACT, bool RESID>
__device__ __forceinline__ void lin44(int Woff, int boff,
                                      const float (&src)[4][4], float (&dst)[4][4]) {
    float4 b = ld4c(boff);
    float acc[4][4];
#pragma unroll
    for (int r = 0; r < 4; r++) {
        acc[r][0] = b.x; acc[r][1] = b.y; acc[r][2] = b.z; acc[r][3] = b.w;
    }
#pragma unroll
    for (int i = 0; i < 4; i++) {
        float4 w = ld4c(Woff + 4 * i);
#pragma unroll
        for (int r = 0; r < 4; r++) {
            acc[r][0] = fmaf(src[r][i], w.x, acc[r][0]);
            acc[r][1] = fmaf(src[r][i], w.y, acc[r][1]);
            acc[r][2] = fmaf(src[r][i], w.z, acc[r][2]);
            acc[r][3] = fmaf(src[r][i], w.w, acc[r][3]);
        }
    }
#pragma unroll
    for (int r = 0; r < 4; r++)
#pragma unroll
        for (int j = 0; j < 4; j++)
            dst[r][j] = RESID ? (dst[r][j] + acc[r][j]) : (ACT ? rr(acc[r][j]) : acc[r][j]);
}

template<bool GUARD>
__global__ __launch_bounds__(NTH)
void ann_fused_kernel(const float* __restrict__ xin, float* __restrict__ out, int N) {
    unsigned base = blockIdx.x * (4 * NTH) + threadIdx.x;

    // ---- load ALL 4 rows up front (8 x LDG.128, kept as float4: 32 regs) ----
    float4 A0[4], A1[4];
#pragma unroll
    for (int r = 0; r < 4; r++) {
        unsigned row = base + r * NTH;
        if (!GUARD || row < (unsigned)N) {
            A0[r] = __ldcs(reinterpret_cast<const float4*>(xin + (size_t)row * 8));
            A1[r] = __ldcs(reinterpret_cast<const float4*>(xin + (size_t)row * 8 + 4));
        } else {
            A0[r] = make_float4(0.f,0.f,0.f,0.f);
            A1[r] = make_float4(0.f,0.f,0.f,0.f);
        }
    }

    // ---- fused in+h1, j-OUTER over the 8 hidden units:
    //      head weights loaded ONCE, 4 independent v-chains per j ----
    float x[4][4];
    {
        float4 bh1 = ld4c(O_B_H1);
#pragma unroll
        for (int r = 0; r < 4; r++) {
            x[r][0]=bh1.x; x[r][1]=bh1.y; x[r][2]=bh1.z; x[r][3]=bh1.w;
        }
#pragma unroll
        for (int j = 0; j < 8; j++) {
            float bj = c_s[O_B_IN + j];
            float4 w0 = ld4c(O_WIN_T + j * 8);
            float4 w1 = ld4c(O_WIN_T + j * 8 + 4);
            float v[4];
#pragma unroll
            for (int r = 0; r < 4; r++) {
                float a = bj;
                a = fmaf(A0[r].x, w0.x, a); a = fmaf(A0[r].y, w0.y, a);
                a = fmaf(A0[r].z, w0.z, a); a = fmaf(A0[r].w, w0.w, a);
                a = fmaf(A1[r].x, w1.x, a); a = fmaf(A1[r].y, w1.y, a);
                a = fmaf(A1[r].z, w1.z, a); a = fmaf(A1[r].w, w1.w, a);
                v[r] = rr(a);
            }
            float4 h = ld4c(O_W_H1 + j * 4);
#pragma unroll
            for (int r = 0; r < 4; r++) {
                x[r][0] = fmaf(v[r], h.x, x[r][0]);
                x[r][1] = fmaf(v[r], h.y, x[r][1]);
                x[r][2] = fmaf(v[r], h.z, x[r][2]);
                x[r][3] = fmaf(v[r], h.w, x[r][3]);
            }
        }
    }
    // A0/A1 dead from here; only 4-wide state remains.

    float t[4][4];

    // ---- encoder residual blocks ----
    lin44<true,  false>(O_W_H2, O_B_H2, x, t);
    lin44<false, true >(O_W_H3, O_B_H3, t, x);
    lin44<true,  false>(O_W_H4, O_B_H4, x, t);
    lin44<false, true >(O_W_H5, O_B_H5, t, x);

    // ---- encode (4 -> 1) + store ----
    float e[4];
    {
        float4 we = ld4c(O_W_EN);
        float be = c_s[O_B_EN];
#pragma unroll
        for (int r = 0; r < 4; r++) {
            float v = be;
            v = fmaf(x[r][0], we.x, v); v = fmaf(x[r][1], we.y, v);
            v = fmaf(x[r][2], we.z, v); v = fmaf(x[r][3], we.w, v);
            e[r] = rr(v);
        }
    }
#pragma unroll
    for (int r = 0; r < 4; r++) {
        unsigned row = base + r * NTH;
        if (!GUARD || row < (unsigned)N) __stcs(out + row, e[r]);
    }

    // ---- h6 (1 -> 4) ----
    {
        float4 w6 = ld4c(O_W_H6);
        float4 b6 = ld4c(O_B_H6);
#pragma unroll
        for (int r = 0; r < 4; r++) {
            x[r][0] = rr(fmaf(e[r], w6.x, b6.x));
            x[r][1] = rr(fmaf(e[r], w6.y, b6.y));
            x[r][2] = rr(fmaf(e[r], w6.z, b6.z));
            x[r][3] = rr(fmaf(e[r], w6.w, b6.w));
        }
    }

    // ---- decoder residual blocks ----
    lin44<true,  false>(O_W_H7, O_B_H7, x, t);
    lin44<false, true >(O_W_H8, O_B_H8, t, x);
    lin44<true,  false>(O_W_H9, O_B_H9, x, t);
    lin44<false, true >(O_W_HA, O_B_HA, t, x);

    // ---- decode (4 -> 8) + store, 2 rows at a time; biases hoisted ----
    float* __restrict__ dec = out + N;
    float4 bd0 = ld4c(O_B_DE);
    float4 bd1 = ld4c(O_B_DE + 4);
#pragma unroll
    for (int pp = 0; pp < 2; pp++) {
        float da[8], db[8];
        da[0]=bd0.x; da[1]=bd0.y; da[2]=bd0.z; da[3]=bd0.w;
        da[4]=bd1.x; da[5]=bd1.y; da[6]=bd1.z; da[7]=bd1.w;
#pragma unroll
        for (int j = 0; j < 8; j++) db[j] = da[j];
#pragma unroll
        for (int i = 0; i < 4; i++) {
            float4 w0 = ld4c(O_W_DE + i * 8);
            float4 w1 = ld4c(O_W_DE + i * 8 + 4);
            float va = x[2*pp][i], vb = x[2*pp+1][i];
            da[0] = fmaf(va, w0.x, da[0]); db[0] = fmaf(vb, w0.x, db[0]);
            da[1] = fmaf(va, w0.y, da[1]); db[1] = fmaf(vb, w0.y, db[1]);
            da[2] = fmaf(va, w0.z, da[2]); db[2] = fmaf(vb, w0.z, db[2]);
            da[3] = fmaf(va, w0.w, da[3]); db[3] = fmaf(vb, w0.w, db[3]);
            da[4] = fmaf(va, w1.x, da[4]); db[4] = fmaf(vb, w1.x, db[4]);
            da[5] = fmaf(va, w1.y, da[5]); db[5] = fmaf(vb, w1.y, db[5]);
            da[6] = fmaf(va, w1.z, da[6]); db[6] = fmaf(vb, w1.z, db[6]);
            da[7] = fmaf(va, w1.w, da[7]); db[7] = fmaf(vb, w1.w, db[7]);
        }
        unsigned rA = base + (2 * pp) * NTH;
        unsigned rB = rA + NTH;
        if (!GUARD || rA < (unsigned)N) {
            __stcs(reinterpret_cast<float4*>(dec + (size_t)rA * 8),
                   make_float4(rr(da[0]), rr(da[1]), rr(da[2]), rr(da[3])));
            __stcs(reinterpret_cast<float4*>(dec + (size_t)rA * 8 + 4),
                   make_float4(rr(da[4]), rr(da[5]), rr(da[6]), rr(da[7])));
        }
        if (!GUARD || rB < (unsigned)N) {
            __stcs(reinterpret_cast<float4*>(dec + (size_t)rB * 8),
                   make_float4(rr(db[0]), rr(db[1]), rr(db[2]), rr(db[3])));
            __stcs(reinterpret_cast<float4*>(dec + (size_t)rB * 8 + 4),
                   make_float4(rr(db[4]), rr(db[5]), rr(db[6]), rr(db[7])));
        }
    }
}

extern "C" void kernel_launch(void* const* d_in, const int* in_sizes, int n_in,
                              void* d_out, int out_size) {
    Params P;
    for (int k = 0; k < 27; k++) P.p[k] = (const float*)d_in[k];
    int N = in_sizes[0] / 8;                 // 4194304 rows

    gather_weights<<<1, 352>>>(P);
    void* stage_ptr = nullptr;
    cudaGetSymbolAddress(&stage_ptr, g_stage);
    cudaMemcpyToSymbolAsync(c_s, stage_ptr, S_TOTAL * sizeof(float), 0,
                            cudaMemcpyDeviceToDevice, 0);

    int rows_per_block = 4 * NTH;            // 1024
    int blocks = (N + rows_per_block - 1) / rows_per_block;
    if (N % rows_per_block == 0)
        ann_fused_kernel<false><<<blocks, NTH>>>((const float*)d_in[0], (float*)d_out, N);
    else
        ann_fused_kernel<true ><<<blocks, NTH>>>((const float*)d_in[0], (float*)d_out, N);
}